// round 13
// baseline (speedup 1.0000x reference)
#include <cuda_runtime.h>
#include <cuda_fp16.h>
#include <cstdint>

#define Nn 2048
#define Bb 64
#define Tt 128
#define Ii 4
#define NSENS 256
#define NOUT 128
#define Oo 2
#define KMICRO 4
#define NBLK 256
#define NTHREADS 256
#define MTILE 64           // neurons per CTA tile (N dim of MMA)
#define KSLICE 256         // k per CTA (split-K 8)
#define ROWB 528           // padded smem row stride (bytes) for 256 fp16

// dynamic smem layout (relative to 1024-aligned base): ~100KB -> 2 CTAs/SM
#define OFF_WHI 0
#define OFF_WLO (MTILE * ROWB)             // 33792
#define OFF_H   (2 * MTILE * ROWB)         // 67584
#define SMEM_BYTES (OFF_H + Bb * ROWB + 1024)   // 102400

// global state: triple-buffered raw accumulators acc[b][n] (pre-relu sums)
__device__ __align__(128) float g_acc[3][Bb * Nn];
__device__ unsigned g_count;
__device__ volatile unsigned g_gen;

__global__ void hx_init_kernel() {
    int i = blockIdx.x * blockDim.x + threadIdx.x;
    if (i == 0) { g_count = 0u; g_gen = 0u; }
    int stride = gridDim.x * blockDim.x;
    for (int j = i; j < 3 * Bb * Nn; j += stride)
        ((float*)g_acc)[j] = 0.0f;
}

// grid barrier: single release fence per CTA (tid 0)
__device__ __forceinline__ void grid_barrier(unsigned step) {
    __syncthreads();
    if (threadIdx.x == 0) {
        __threadfence();                     // publish this CTA's REDGs
        unsigned a = atomicAdd(&g_count, 1u);
        if (a == (unsigned)(gridDim.x - 1)) {
            g_count = 0u;
            __threadfence();
            g_gen = step;
        } else {
            while (g_gen < step) { }
            __threadfence();                 // acquire
        }
    }
    __syncthreads();
}

__device__ __forceinline__ uint32_t smem_u32(const void* p) {
    uint32_t a;
    asm("{ .reg .u64 t; cvta.to.shared.u64 t, %1; cvt.u32.u64 %0, t; }"
        : "=r"(a) : "l"(p));
    return a;
}

__device__ __forceinline__ void ldm4(uint32_t* r, uint32_t addr) {
    asm volatile("ldmatrix.sync.aligned.m8n8.x4.shared.b16 {%0,%1,%2,%3}, [%4];"
                 : "=r"(r[0]), "=r"(r[1]), "=r"(r[2]), "=r"(r[3]) : "r"(addr));
}

__device__ __forceinline__ void mma_fp16(float* c, const uint32_t* a,
                                         uint32_t b0, uint32_t b1) {
    asm volatile("mma.sync.aligned.m16n8k16.row.col.f32.f16.f16.f32 "
                 "{%0,%1,%2,%3}, {%4,%5,%6,%7}, {%8,%9}, {%0,%1,%2,%3};"
                 : "+f"(c[0]), "+f"(c[1]), "+f"(c[2]), "+f"(c[3])
                 : "r"(a[0]), "r"(a[1]), "r"(a[2]), "r"(a[3]),
                   "r"(b0), "r"(b1));
}

__device__ __forceinline__ void redg4(float* p, float v0, float v1,
                                      float v2, float v3) {
    asm volatile("red.global.add.v4.f32 [%0], {%1,%2,%3,%4};"
                 :: "l"(p), "f"(v0), "f"(v1), "f"(v2), "f"(v3) : "memory");
}

__global__ void __launch_bounds__(NTHREADS, 2) hx_rnn_kernel(
    const float* __restrict__ inputs,   // [B, T, I]
    const float* __restrict__ W,        // [N, N]
    const float* __restrict__ W_in,     // [NSENS, I]
    const float* __restrict__ b_in,     // [NSENS]
    const float* __restrict__ W_out,    // [O, NOUT]
    const float* __restrict__ b_out,    // [O]
    const void*  sens_idx_p,
    const void*  out_idx_p,
    float* __restrict__ out)            // [B, T, O]
{
    extern __shared__ char raw[];
    const uint32_t raw_u = smem_u32(raw);
    const uint32_t dyn_u = (raw_u + 1023u) & ~1023u;
    char* dyn = raw + (dyn_u - raw_u);

    __shared__ int s_kslot[KSLICE];     // local k -> sensory slot (or -1)
    __shared__ int s_out_idx[NOUT];
    __shared__ float s_wout[Oo * NOUT];
    __shared__ float4 s_win[NSENS];
    __shared__ float s_bin[NSENS];
    __shared__ int s_flags;

    const int tid = threadIdx.x;
    const int blk = blockIdx.x;
    const int mt = blk >> 3;            // n-tile (neurons, 64 each) 0..31
    const int ks = blk & 7;             // k-slice 0..7

    // ---- index dtype detection (int64 vs int32) ----
    if (tid == 0) {
        const int* ws = (const int*)sens_idx_p;
        int s64 = 1;
        for (int i = 1; i < NSENS; i += 2) { if (ws[i] != 0) { s64 = 0; break; } }
        const int* wo = (const int*)out_idx_p;
        int o64 = 1;
        for (int i = 1; i < NOUT; i += 2) { if (wo[i] != 0) { o64 = 0; break; } }
        s_flags = s64 | (o64 << 1);
    }
    for (int k = tid; k < KSLICE; k += NTHREADS) s_kslot[k] = -1;
    __syncthreads();
    const bool s64 = (s_flags & 1) != 0;
    const bool o64 = (s_flags & 2) != 0;

    for (int s = tid; s < NSENS; s += NTHREADS) {
        int idx = s64 ? (int)((const long long*)sens_idx_p)[s]
                      : ((const int*)sens_idx_p)[s];
        if (idx >= ks * KSLICE && idx < (ks + 1) * KSLICE)
            s_kslot[idx - ks * KSLICE] = s;
        s_win[s] = *(const float4*)(W_in + s * Ii);
        s_bin[s] = b_in[s];
    }
    for (int j = tid; j < NOUT; j += NTHREADS)
        s_out_idx[j] = o64 ? (int)((const long long*)out_idx_p)[j]
                           : ((const int*)out_idx_p)[j];
    for (int j = tid; j < Oo * NOUT; j += NTHREADS) s_wout[j] = W_out[j];

    // ---- one-time: W tile -> fp16 hi/lo, padded rows in smem ----
    for (int idx = tid; idx < MTILE * KSLICE; idx += NTHREADS) {
        int nl = idx >> 8;              // /256 -> 0..63
        int k  = idx & 255;
        float w = __ldg(W + (size_t)(mt * MTILE + nl) * Nn + ks * KSLICE + k);
        __half hi = __float2half_rn(w);
        __half lo = __float2half_rn(w - __half2float(hi));
        *(__half*)(dyn + OFF_WHI + nl * ROWB + k * 2) = hi;
        *(__half*)(dyn + OFF_WLO + nl * ROWB + k * 2) = lo;
    }
    __syncthreads();

    // ---- warp/lane mapping: 2(m=batch32) x 4(n=neuron16) warp grid ----
    const int w  = tid >> 5;
    const int l  = tid & 31;
    const int warp_m = w >> 2;          // 0..1 -> 32 batch rows
    const int warp_n = w & 3;           // 0..3 -> 16 neuron cols
    // A operand = h tile [b][k], m16k16 ldmatrix x4
    const uint32_t hAddr = dyn_u + OFF_H
        + (uint32_t)((warp_m * 32 + (l & 15)) * ROWB + (l >> 4) * 16);
    // B operand = W tile [n][k], n16k16 ldmatrix x4
    const uint32_t wHiAddr = dyn_u + OFF_WHI
        + (uint32_t)((warp_n * 16 + (l & 7) + ((l >> 4) << 3)) * ROWB
                     + ((l >> 3) & 1) * 16);
    const uint32_t wLoAddr = wHiAddr + (OFF_WLO - OFF_WHI);

    // stage mapping: thread -> (batch, k-group of 4 per 16)
    const int b_s = tid >> 2;           // 0..63
    const int kg  = tid & 3;

    // epilogue (REDG v4) coordinates: acc[b][n]
    const int b_e = warp_m * 32 + (l >> 2) + (l & 1) * 8;
    const int n_e = mt * MTILE + warp_n * 16 + ((l & 3) >> 1) * 4;
    const bool odd = (l & 1) != 0;

    unsigned step = 1;

    for (int t = 0; t < Tt; ++t) {
        for (int mi = 0; mi < KMICRO; ++mi) {
            const int g = t * KMICRO + mi;
            const float* acc_prev = g_acc[(g + 2) % 3];
            float* acc_cur  = g_acc[g % 3];
            float* acc_zero = g_acc[(g + 1) % 3];

            // ---- stage: read raw sums, inject+relu, fp16 -> smem ----
            {
                float4 xv = make_float4(0.f, 0.f, 0.f, 0.f);
                if (mi == 0)
                    xv = *(const float4*)(inputs + (size_t)b_s * (Tt * Ii) + t * Ii);
                const float* ap = acc_prev + (size_t)b_s * Nn + ks * KSLICE;
                char* bh = dyn + OFF_H + b_s * ROWB;

                // zero the buffer that will be REDG'd next microstep
                *(float2*)(acc_zero + blk * (NTHREADS * 2) + tid * 2)
                    = make_float2(0.f, 0.f);

                #pragma unroll
                for (int batch = 0; batch < 2; ++batch) {
                    float4 qv[8];
                    #pragma unroll
                    for (int i = 0; i < 8; ++i)
                        qv[i] = __ldcg((const float4*)(ap + kg * 4
                                                       + (batch * 8 + i) * 16));
                    #pragma unroll
                    for (int i = 0; i < 8; ++i) {
                        const int k0 = kg * 4 + (batch * 8 + i) * 16;
                        float vj[4] = {qv[i].x, qv[i].y, qv[i].z, qv[i].w};
                        if (mi == 0) {
                            #pragma unroll
                            for (int j = 0; j < 4; ++j) {
                                int s = s_kslot[k0 + j];
                                if (s >= 0) {
                                    float4 wv = s_win[s];
                                    vj[j] += s_bin[s] + wv.x * xv.x + wv.y * xv.y
                                           + wv.z * xv.z + wv.w * xv.w;
                                }
                            }
                        }
                        __half2 p0 = __floats2half2_rn(fmaxf(vj[0], 0.f),
                                                       fmaxf(vj[1], 0.f));
                        __half2 p1 = __floats2half2_rn(fmaxf(vj[2], 0.f),
                                                       fmaxf(vj[3], 0.f));
                        *(uint2*)(bh + k0 * 2)
                            = make_uint2(*(uint32_t*)&p0, *(uint32_t*)&p1);
                    }
                }
            }
            __syncthreads();

            // ---- readout for timestep t (blocks 0..127 only) ----
            if (mi == KMICRO - 1 && w == 0 && blk < 128) {
                const int o = blk >> 6;
                const int bb = blk & 63;
                const float* hr = acc_prev + (size_t)bb * Nn;
                float a = 0.0f;
                #pragma unroll
                for (int jj = 0; jj < 4; ++jj) {
                    int j = l + jj * 32;
                    float hv;
                    asm volatile("ld.global.cg.f32 %0, [%1];"
                                 : "=f"(hv) : "l"(hr + s_out_idx[j]));
                    a += s_wout[o * NOUT + j] * fmaxf(hv, 0.f);
                }
                #pragma unroll
                for (int off = 16; off > 0; off >>= 1)
                    a += __shfl_xor_sync(0xFFFFFFFFu, a, off);
                if (l == 0)
                    out[(size_t)bb * (Tt * Oo) + t * Oo + o] = a + b_out[o];
            }

            // ---- MMA + v4 REDG epilogue (skipped on final microstep) ----
            if (!(t == Tt - 1 && mi == KMICRO - 1)) {
                float facc[2][2][4];
                #pragma unroll
                for (int i = 0; i < 2; ++i)
                    #pragma unroll
                    for (int j = 0; j < 2; ++j)
                        #pragma unroll
                        for (int q = 0; q < 4; ++q) facc[i][j][q] = 0.0f;

                #pragma unroll 4
                for (int k = 0; k < 16; ++k) {
                    const uint32_t ko = (uint32_t)k * 32u;
                    uint32_t ah0[4], ah1[4], wh[4], wl[4];
                    ldm4(ah0, hAddr + ko);
                    ldm4(ah1, hAddr + 16 * ROWB + ko);
                    ldm4(wh, wHiAddr + ko);
                    ldm4(wl, wLoAddr + ko);
                    #pragma unroll
                    for (int nf = 0; nf < 2; ++nf) {
                        mma_fp16(facc[0][nf], ah0, wh[2 * nf], wh[2 * nf + 1]);
                        mma_fp16(facc[1][nf], ah1, wh[2 * nf], wh[2 * nf + 1]);
                        mma_fp16(facc[0][nf], ah0, wl[2 * nf], wl[2 * nf + 1]);
                        mma_fp16(facc[1][nf], ah1, wl[2 * nf], wl[2 * nf + 1]);
                    }
                }

                #pragma unroll
                for (int m2 = 0; m2 < 2; ++m2) {
                    #pragma unroll
                    for (int nf = 0; nf < 2; ++nf) {
                        float c0 = facc[m2][nf][0], c1 = facc[m2][nf][1];
                        float c2 = facc[m2][nf][2], c3 = facc[m2][nf][3];
                        float p0 = __shfl_xor_sync(0xFFFFFFFFu, c0, 1);
                        float p1 = __shfl_xor_sync(0xFFFFFFFFu, c1, 1);
                        float p2 = __shfl_xor_sync(0xFFFFFFFFu, c2, 1);
                        float p3 = __shfl_xor_sync(0xFFFFFFFFu, c3, 1);
                        float v0 = odd ? p2 : c0;
                        float v1 = odd ? p3 : c1;
                        float v2 = odd ? c2 : p0;
                        float v3 = odd ? c3 : p1;
                        redg4(acc_cur + (size_t)(b_e + m2 * 16) * Nn
                              + (n_e + nf * 8), v0, v1, v2, v3);
                    }
                }
            }

            grid_barrier(step++);
        }
    }
}

extern "C" void kernel_launch(void* const* d_in, const int* in_sizes, int n_in,
                              void* d_out, int out_size) {
    (void)in_sizes; (void)n_in; (void)out_size;
    const float* inputs = (const float*)d_in[0];
    const float* W_rec  = (const float*)d_in[1];
    const float* W_in   = (const float*)d_in[2];
    const float* b_in   = (const float*)d_in[3];
    const float* W_out  = (const float*)d_in[4];
    const float* b_out  = (const float*)d_in[5];
    const void*  s_idx  = d_in[6];
    const void*  o_idx  = d_in[7];

    cudaFuncSetAttribute(hx_rnn_kernel,
                         cudaFuncAttributeMaxDynamicSharedMemorySize, SMEM_BYTES);

    hx_init_kernel<<<128, 256>>>();
    hx_rnn_kernel<<<NBLK, NTHREADS, SMEM_BYTES>>>(inputs, W_rec, W_in, b_in,
                                                  W_out, b_out, s_idx, o_idx,
                                                  (float*)d_out);
}

// round 14
// speedup vs baseline: 1.1991x; 1.1991x over previous
#include <cuda_runtime.h>
#include <cuda_fp16.h>
#include <cstdint>

#define Nn 2048
#define Bb 64
#define Tt 128
#define Ii 4
#define NSENS 256
#define NOUT 128
#define Oo 2
#define KMICRO 4
#define NBLK 128
#define NTHREADS 512
#define MTILE 128          // neurons per CTA tile (N dim of MMA)
#define KSLICE 256         // k per CTA (split-K 8)
#define ROWB 528           // padded smem row stride (bytes) for 256 fp16

// dynamic smem layout (relative to 1024-aligned base)
#define OFF_WHI 0
#define OFF_WLO (MTILE * ROWB)             // 67584
#define OFF_H   (2 * MTILE * ROWB)         // 135168
#define SMEM_BYTES (OFF_H + Bb * ROWB + 1024)   // 169984

// global state: triple-buffered raw accumulators acc[b][n] (pre-relu sums)
__device__ __align__(128) float g_acc[3][Bb * Nn];
__device__ unsigned g_count;
__device__ volatile unsigned g_gen;

__global__ void hx_init_kernel() {
    int i = blockIdx.x * blockDim.x + threadIdx.x;
    if (i == 0) { g_count = 0u; g_gen = 0u; }
    int stride = gridDim.x * blockDim.x;
    for (int j = i; j < 3 * Bb * Nn; j += stride)
        ((float*)g_acc)[j] = 0.0f;
}

// grid barrier: single release fence per CTA (tid 0)
__device__ __forceinline__ void grid_barrier(unsigned step) {
    __syncthreads();
    if (threadIdx.x == 0) {
        __threadfence();                     // publish this CTA's REDGs
        unsigned a = atomicAdd(&g_count, 1u);
        if (a == (unsigned)(gridDim.x - 1)) {
            g_count = 0u;
            __threadfence();
            g_gen = step;
        } else {
            while (g_gen < step) { }
            __threadfence();                 // acquire
        }
    }
    __syncthreads();
}

__device__ __forceinline__ uint32_t smem_u32(const void* p) {
    uint32_t a;
    asm("{ .reg .u64 t; cvta.to.shared.u64 t, %1; cvt.u32.u64 %0, t; }"
        : "=r"(a) : "l"(p));
    return a;
}

__device__ __forceinline__ void ldm4(uint32_t* r, uint32_t addr) {
    asm volatile("ldmatrix.sync.aligned.m8n8.x4.shared.b16 {%0,%1,%2,%3}, [%4];"
                 : "=r"(r[0]), "=r"(r[1]), "=r"(r[2]), "=r"(r[3]) : "r"(addr));
}

__device__ __forceinline__ void mma_fp16(float* c, const uint32_t* a,
                                         uint32_t b0, uint32_t b1) {
    asm volatile("mma.sync.aligned.m16n8k16.row.col.f32.f16.f16.f32 "
                 "{%0,%1,%2,%3}, {%4,%5,%6,%7}, {%8,%9}, {%0,%1,%2,%3};"
                 : "+f"(c[0]), "+f"(c[1]), "+f"(c[2]), "+f"(c[3])
                 : "r"(a[0]), "r"(a[1]), "r"(a[2]), "r"(a[3]),
                   "r"(b0), "r"(b1));
}

__device__ __forceinline__ void redg4(float* p, float v0, float v1,
                                      float v2, float v3) {
    asm volatile("red.global.add.v4.f32 [%0], {%1,%2,%3,%4};"
                 :: "l"(p), "f"(v0), "f"(v1), "f"(v2), "f"(v3) : "memory");
}

__global__ void __launch_bounds__(NTHREADS, 1) hx_rnn_kernel(
    const float* __restrict__ inputs,   // [B, T, I]
    const float* __restrict__ W,        // [N, N]
    const float* __restrict__ W_in,     // [NSENS, I]
    const float* __restrict__ b_in,     // [NSENS]
    const float* __restrict__ W_out,    // [O, NOUT]
    const float* __restrict__ b_out,    // [O]
    const void*  sens_idx_p,
    const void*  out_idx_p,
    float* __restrict__ out)            // [B, T, O]
{
    extern __shared__ char raw[];
    const uint32_t raw_u = smem_u32(raw);
    const uint32_t dyn_u = (raw_u + 1023u) & ~1023u;
    char* dyn = raw + (dyn_u - raw_u);

    __shared__ int s_kslot[KSLICE];     // local k -> sensory slot (or -1)
    __shared__ int s_out_idx[NOUT];
    __shared__ float s_wout[Oo * NOUT];
    __shared__ float4 s_win[NSENS];
    __shared__ float s_bin[NSENS];
    __shared__ int s_flags;

    const int tid = threadIdx.x;
    const int blk = blockIdx.x;
    const int mt = blk >> 3;            // n-tile (neurons) 0..15
    const int ks = blk & 7;             // k-slice 0..7

    // ---- index dtype detection (int64 vs int32) ----
    if (tid == 0) {
        const int* ws = (const int*)sens_idx_p;
        int s64 = 1;
        for (int i = 1; i < NSENS; i += 2) { if (ws[i] != 0) { s64 = 0; break; } }
        const int* wo = (const int*)out_idx_p;
        int o64 = 1;
        for (int i = 1; i < NOUT; i += 2) { if (wo[i] != 0) { o64 = 0; break; } }
        s_flags = s64 | (o64 << 1);
    }
    for (int k = tid; k < KSLICE; k += NTHREADS) s_kslot[k] = -1;
    __syncthreads();
    const bool s64 = (s_flags & 1) != 0;
    const bool o64 = (s_flags & 2) != 0;

    for (int s = tid; s < NSENS; s += NTHREADS) {
        int idx = s64 ? (int)((const long long*)sens_idx_p)[s]
                      : ((const int*)sens_idx_p)[s];
        if (idx >= ks * KSLICE && idx < (ks + 1) * KSLICE)
            s_kslot[idx - ks * KSLICE] = s;
        s_win[s] = *(const float4*)(W_in + s * Ii);
        s_bin[s] = b_in[s];
    }
    for (int j = tid; j < NOUT; j += NTHREADS)
        s_out_idx[j] = o64 ? (int)((const long long*)out_idx_p)[j]
                           : ((const int*)out_idx_p)[j];
    for (int j = tid; j < Oo * NOUT; j += NTHREADS) s_wout[j] = W_out[j];

    // ---- one-time: W tile -> fp16 hi/lo, padded rows in smem ----
    for (int idx = tid; idx < MTILE * KSLICE; idx += NTHREADS) {
        int nl = idx >> 8;              // /256
        int k  = idx & 255;
        float w = __ldg(W + (size_t)(mt * MTILE + nl) * Nn + ks * KSLICE + k);
        __half hi = __float2half_rn(w);
        __half lo = __float2half_rn(w - __half2float(hi));
        *(__half*)(dyn + OFF_WHI + nl * ROWB + k * 2) = hi;
        *(__half*)(dyn + OFF_WLO + nl * ROWB + k * 2) = lo;
    }
    __syncthreads();

    // ---- warp/lane mapping: 2(m=batch32) x 8(n=neuron16) warp grid ----
    const int w  = tid >> 5;
    const int l  = tid & 31;
    const int warp_m = w >> 3;          // 0..1 -> 32 batch rows
    const int warp_n = w & 7;           // 0..7 -> 16 neuron cols
    // A operand = h tile [b][k], m16k16 ldmatrix x4
    const uint32_t hAddr = dyn_u + OFF_H
        + (uint32_t)((warp_m * 32 + (l & 15)) * ROWB + (l >> 4) * 16);
    // B operand = W tile [n][k], n16k16 ldmatrix x4
    const uint32_t wHiAddr = dyn_u + OFF_WHI
        + (uint32_t)((warp_n * 16 + (l & 7) + ((l >> 4) << 3)) * ROWB
                     + ((l >> 3) & 1) * 16);
    const uint32_t wLoAddr = wHiAddr + (OFF_WLO - OFF_WHI);

    // ---- persist W-hi fragments for k16 steps 0..7 in registers (32 regs) ----
    uint32_t whr[8][4];
    #pragma unroll
    for (int k = 0; k < 8; ++k)
        ldm4(whr[k], wHiAddr + (uint32_t)k * 32u);

    // stage mapping: thread -> (batch, 8-k segment): b 64 x j 8
    const int b_s = tid >> 3;           // 0..63
    const int jj  = tid & 7;            // 8 consecutive k each, per i-quarter

    // epilogue (REDG v4) coordinates: acc[b][n]
    const int b_e = warp_m * 32 + (l >> 2) + (l & 1) * 8;
    const int n_e = mt * MTILE + warp_n * 16 + ((l & 3) >> 1) * 4;
    const bool odd = (l & 1) != 0;

    unsigned step = 1;

    for (int t = 0; t < Tt; ++t) {
        for (int mi = 0; mi < KMICRO; ++mi) {
            const int g = t * KMICRO + mi;
            const float* acc_prev = g_acc[(g + 2) % 3];
            float* acc_cur  = g_acc[g % 3];
            float* acc_zero = g_acc[(g + 1) % 3];

            // ---- stage: read raw sums, inject+relu, fp16 -> smem (STS.128) ----
            {
                const float* ap = acc_prev + (size_t)b_s * Nn + ks * KSLICE;
                float4 qv[8];
                #pragma unroll
                for (int i = 0; i < 4; ++i) {
                    const int k0 = jj * 8 + i * 64;
                    qv[i * 2 + 0] = __ldcg((const float4*)(ap + k0));
                    qv[i * 2 + 1] = __ldcg((const float4*)(ap + k0 + 4));
                }

                // zero the buffer that will be REDG'd next microstep
                *(float2*)(acc_zero + blk * (NTHREADS * 2) + tid * 2)
                    = make_float2(0.f, 0.f);

                float4 xv = make_float4(0.f, 0.f, 0.f, 0.f);
                if (mi == 0)
                    xv = *(const float4*)(inputs + (size_t)b_s * (Tt * Ii) + t * Ii);
                char* bh = dyn + OFF_H + b_s * ROWB;
                #pragma unroll
                for (int i = 0; i < 4; ++i) {
                    const int k0 = jj * 8 + i * 64;
                    float vj[8] = {qv[i*2].x, qv[i*2].y, qv[i*2].z, qv[i*2].w,
                                   qv[i*2+1].x, qv[i*2+1].y, qv[i*2+1].z,
                                   qv[i*2+1].w};
                    if (mi == 0) {
                        #pragma unroll
                        for (int j = 0; j < 8; ++j) {
                            int s = s_kslot[k0 + j];
                            if (s >= 0) {
                                float4 wv = s_win[s];
                                vj[j] += s_bin[s] + wv.x * xv.x + wv.y * xv.y
                                       + wv.z * xv.z + wv.w * xv.w;
                            }
                        }
                    }
                    uint32_t u[4];
                    #pragma unroll
                    for (int j = 0; j < 4; ++j) {
                        __half2 h2 = __floats2half2_rn(fmaxf(vj[2 * j], 0.f),
                                                       fmaxf(vj[2 * j + 1], 0.f));
                        u[j] = *(uint32_t*)&h2;
                    }
                    *(uint4*)(bh + k0 * 2) = make_uint4(u[0], u[1], u[2], u[3]);
                }
            }
            __syncthreads();

            // ---- readout for timestep t (overlaps other warps' MMA) ----
            if (mi == KMICRO - 1 && w == 0) {
                const int o = blk >> 6;
                const int bb = blk & 63;
                const float* hr = acc_prev + (size_t)bb * Nn;
                float a = 0.0f;
                #pragma unroll
                for (int jx = 0; jx < 4; ++jx) {
                    int j = l + jx * 32;
                    float hv;
                    asm volatile("ld.global.cg.f32 %0, [%1];"
                                 : "=f"(hv) : "l"(hr + s_out_idx[j]));
                    a += s_wout[o * NOUT + j] * fmaxf(hv, 0.f);
                }
                #pragma unroll
                for (int off = 16; off > 0; off >>= 1)
                    a += __shfl_xor_sync(0xFFFFFFFFu, a, off);
                if (l == 0)
                    out[(size_t)bb * (Tt * Oo) + t * Oo + o] = a + b_out[o];
            }

            // ---- MMA + v4 REDG epilogue (skipped on final microstep) ----
            if (!(t == Tt - 1 && mi == KMICRO - 1)) {
                float facc[2][2][4];
                #pragma unroll
                for (int i = 0; i < 2; ++i)
                    #pragma unroll
                    for (int j = 0; j < 2; ++j)
                        #pragma unroll
                        for (int q = 0; q < 4; ++q) facc[i][j][q] = 0.0f;

                // k16 0..7: W-hi fragments from registers (no wh LDSM)
                #pragma unroll
                for (int k = 0; k < 8; ++k) {
                    const uint32_t ko = (uint32_t)k * 32u;
                    uint32_t ah0[4], ah1[4], wl[4];
                    ldm4(ah0, hAddr + ko);
                    ldm4(ah1, hAddr + 16 * ROWB + ko);
                    ldm4(wl, wLoAddr + ko);
                    #pragma unroll
                    for (int nf = 0; nf < 2; ++nf) {
                        mma_fp16(facc[0][nf], ah0, whr[k][2*nf], whr[k][2*nf+1]);
                        mma_fp16(facc[1][nf], ah1, whr[k][2*nf], whr[k][2*nf+1]);
                        mma_fp16(facc[0][nf], ah0, wl[2 * nf], wl[2 * nf + 1]);
                        mma_fp16(facc[1][nf], ah1, wl[2 * nf], wl[2 * nf + 1]);
                    }
                }
                // k16 8..15: full LDSM path
                #pragma unroll
                for (int k = 8; k < 16; ++k) {
                    const uint32_t ko = (uint32_t)k * 32u;
                    uint32_t ah0[4], ah1[4], wh[4], wl[4];
                    ldm4(ah0, hAddr + ko);
                    ldm4(ah1, hAddr + 16 * ROWB + ko);
                    ldm4(wh, wHiAddr + ko);
                    ldm4(wl, wLoAddr + ko);
                    #pragma unroll
                    for (int nf = 0; nf < 2; ++nf) {
                        mma_fp16(facc[0][nf], ah0, wh[2 * nf], wh[2 * nf + 1]);
                        mma_fp16(facc[1][nf], ah1, wh[2 * nf], wh[2 * nf + 1]);
                        mma_fp16(facc[0][nf], ah0, wl[2 * nf], wl[2 * nf + 1]);
                        mma_fp16(facc[1][nf], ah1, wl[2 * nf], wl[2 * nf + 1]);
                    }
                }

                #pragma unroll
                for (int m2 = 0; m2 < 2; ++m2) {
                    #pragma unroll
                    for (int nf = 0; nf < 2; ++nf) {
                        float c0 = facc[m2][nf][0], c1 = facc[m2][nf][1];
                        float c2 = facc[m2][nf][2], c3 = facc[m2][nf][3];
                        float p0 = __shfl_xor_sync(0xFFFFFFFFu, c0, 1);
                        float p1 = __shfl_xor_sync(0xFFFFFFFFu, c1, 1);
                        float p2 = __shfl_xor_sync(0xFFFFFFFFu, c2, 1);
                        float p3 = __shfl_xor_sync(0xFFFFFFFFu, c3, 1);
                        float v0 = odd ? p2 : c0;
                        float v1 = odd ? p3 : c1;
                        float v2 = odd ? c2 : p0;
                        float v3 = odd ? c3 : p1;
                        redg4(acc_cur + (size_t)(b_e + m2 * 16) * Nn
                              + (n_e + nf * 8), v0, v1, v2, v3);
                    }
                }
            }

            grid_barrier(step++);
        }
    }
}

extern "C" void kernel_launch(void* const* d_in, const int* in_sizes, int n_in,
                              void* d_out, int out_size) {
    (void)in_sizes; (void)n_in; (void)out_size;
    const float* inputs = (const float*)d_in[0];
    const float* W_rec  = (const float*)d_in[1];
    const float* W_in   = (const float*)d_in[2];
    const float* b_in   = (const float*)d_in[3];
    const float* W_out  = (const float*)d_in[4];
    const float* b_out  = (const float*)d_in[5];
    const void*  s_idx  = d_in[6];
    const void*  o_idx  = d_in[7];

    cudaFuncSetAttribute(hx_rnn_kernel,
                         cudaFuncAttributeMaxDynamicSharedMemorySize, SMEM_BYTES);

    hx_init_kernel<<<128, 256>>>();
    hx_rnn_kernel<<<NBLK, NTHREADS, SMEM_BYTES>>>(inputs, W_rec, W_in, b_in,
                                                  W_out, b_out, s_idx, o_idx,
                                                  (float*)d_out);
}